// round 8
// baseline (speedup 1.0000x reference)
#include <cuda_runtime.h>
#include <cstdint>

// T = 2000 tags, V = 20000 videos, D = 768, E_POS = E_NEG = 100000
// Output layout: [cls_score (V*T f32), labels (V*T f32)]
//
// Structure:
//   1) scatter_kernel : bin edges by tag (batched, atomic cursors)
//   2) mega_kernel    : 4000 blocks, roles alternate by bid&1
//        - EDGE role (even): per-tag dots -> g_score scratch (LTS-bound)
//        - ZERO role (odd) : stream 320MB zeros via __stwt (DRAM-bound,
//          write-through so the L2-resident video table is NOT evicted)
//      Roles write disjoint memory -> no ordering hazard.
//   3) fold_kernel    : add ~200k scores + labels into zeroed output,
//                       reset cursors (sole reset point).

#define D_DIM    768
#define T_DIM    2000
#define BIN_CAP  192      // edges/tag ~ Poisson(100); P(>192) ~ 1e-12

__device__ int      g_cursor[T_DIM];
__device__ unsigned g_edges [T_DIM * BIN_CAP];   // bit31 = isPos, low = dst
__device__ float    g_score [T_DIM * BIN_CAP];   // per-edge dot results

// ---------------------------------------------------------------------------
// Batched binning: 4 edges per thread to amortize the load->atomic->store
// latency chain.
// ---------------------------------------------------------------------------
__global__ void scatter_kernel(const int* __restrict__ pos_src,
                               const int* __restrict__ pos_dst,
                               const int* __restrict__ neg_src,
                               const int* __restrict__ neg_dst,
                               int nPos, int nTot) {
    int base = (blockIdx.x * blockDim.x + threadIdx.x) * 4;
#pragma unroll
    for (int k = 0; k < 4; k++) {
        int i = base + k;
        if (i < nTot) {
            int t; unsigned enc;
            if (i < nPos) { t = pos_src[i];        enc = (unsigned)pos_dst[i] | 0x80000000u; }
            else          { t = neg_src[i - nPos]; enc = (unsigned)neg_dst[i - nPos]; }
            int slot = atomicAdd(&g_cursor[t], 1);
            if (slot < BIN_CAP)
                g_edges[t * BIN_CAP + slot] = enc;
        }
    }
}

// ---------------------------------------------------------------------------
__global__ __launch_bounds__(256) void mega_kernel(
    const float* __restrict__ h_tag,
    const float* __restrict__ h_video,
    float4*      __restrict__ out_vec,
    long long    nvec)
{
    const int bid = blockIdx.x;
    const int tid = threadIdx.x;

    if (bid & 1) {
        // ---------------- ZERO role: write-through, no L2 pollution --------
        long long zid  = bid >> 1;                    // 0..1999
        const long long stride = 2000LL * 256LL;
        const float4 z = make_float4(0.f, 0.f, 0.f, 0.f);
        for (long long i = zid * 256 + tid; i < nvec; i += stride)
            __stwt(&out_vec[i], z);
        return;
    }

    // ------------------- EDGE role: one tag per block ----------------------
    const int t = bid >> 1;
    __shared__ float4 stag[D_DIM / 4];
    __shared__ int    s_n;

    if (tid == 0) {
        int c = g_cursor[t];          // READ ONLY -- fold_kernel resets it
        s_n = (c > BIN_CAP) ? BIN_CAP : c;
    }
    if (tid < D_DIM / 4)
        stag[tid] = reinterpret_cast<const float4*>(h_tag + (size_t)t * D_DIM)[tid];
    __syncthreads();

    const int lane = tid & 31;
    const int warp = tid >> 5;

    // tag row -> registers
    float4 ta0 = stag[lane +   0];
    float4 ta1 = stag[lane +  32];
    float4 ta2 = stag[lane +  64];
    float4 ta3 = stag[lane +  96];
    float4 ta4 = stag[lane + 128];
    float4 ta5 = stag[lane + 160];

    const int n = s_n;
    const unsigned* elist = g_edges + (size_t)t * BIN_CAP;
    float*          slist = g_score + (size_t)t * BIN_CAP;

    int i = warp;
    if (i >= n) return;

    unsigned enc = elist[i];
    const float4* bp =
        reinterpret_cast<const float4*>(h_video + (size_t)(enc & 0x7fffffffu) * D_DIM);
    float4 v0 = bp[lane +   0];
    float4 v1 = bp[lane +  32];
    float4 v2 = bp[lane +  64];
    float4 v3 = bp[lane +  96];
    float4 v4 = bp[lane + 128];
    float4 v5 = bp[lane + 160];

    while (true) {
        const int inext = i + 8;               // 8 warps per block
        const bool more = inext < n;

        // prefetch next edge's video row during the reduce
        unsigned enc_n = 0;
        float4 w0, w1, w2, w3, w4, w5;
        if (more) {
            enc_n = elist[inext];
            const float4* bn =
                reinterpret_cast<const float4*>(h_video + (size_t)(enc_n & 0x7fffffffu) * D_DIM);
            w0 = bn[lane +   0];
            w1 = bn[lane +  32];
            w2 = bn[lane +  64];
            w3 = bn[lane +  96];
            w4 = bn[lane + 128];
            w5 = bn[lane + 160];
        }

        float acc;
        acc  = ta0.x * v0.x + ta0.y * v0.y + ta0.z * v0.z + ta0.w * v0.w;
        acc += ta1.x * v1.x + ta1.y * v1.y + ta1.z * v1.z + ta1.w * v1.w;
        acc += ta2.x * v2.x + ta2.y * v2.y + ta2.z * v2.z + ta2.w * v2.w;
        acc += ta3.x * v3.x + ta3.y * v3.y + ta3.z * v3.z + ta3.w * v3.w;
        acc += ta4.x * v4.x + ta4.y * v4.y + ta4.z * v4.z + ta4.w * v4.w;
        acc += ta5.x * v5.x + ta5.y * v5.y + ta5.z * v5.z + ta5.w * v5.w;

#pragma unroll
        for (int off = 16; off > 0; off >>= 1)
            acc += __shfl_xor_sync(0xffffffffu, acc, off);

        if (lane == 0) slist[i] = acc;

        if (!more) break;
        i = inext; enc = enc_n;
        v0 = w0; v1 = w1; v2 = w2; v3 = w3; v4 = w4; v5 = w5;
    }
}

// ---------------------------------------------------------------------------
// Fold ~200k per-edge scores + labels into the zeroed output; reset cursors.
// ---------------------------------------------------------------------------
__global__ void fold_kernel(float* __restrict__ cls,
                            float* __restrict__ labels)
{
    int t = blockIdx.x;
    __shared__ int s_n;
    if (threadIdx.x == 0) {
        int c = g_cursor[t];
        s_n = (c > BIN_CAP) ? BIN_CAP : c;
        g_cursor[t] = 0;                 // sole reset point (for next replay)
    }
    __syncthreads();
    int n = s_n;
    for (int i = threadIdx.x; i < n; i += blockDim.x) {
        unsigned enc = g_edges[t * BIN_CAP + i];
        float    sc  = g_score[t * BIN_CAP + i];
        size_t cell = (size_t)(enc & 0x7fffffffu) * T_DIM + (size_t)t;
        atomicAdd(&cls[cell], sc);
        if (enc & 0x80000000u) atomicAdd(&labels[cell], 1.0f);
    }
}

// ---------------------------------------------------------------------------
extern "C" void kernel_launch(void* const* d_in, const int* in_sizes, int n_in,
                              void* d_out, int out_size)
{
    const float* h_tag   = (const float*)d_in[0];
    const float* h_video = (const float*)d_in[1];
    const int*   pos_src = (const int*)d_in[2];
    const int*   pos_dst = (const int*)d_in[3];
    const int*   neg_src = (const int*)d_in[4];
    const int*   neg_dst = (const int*)d_in[5];

    const int nPos = in_sizes[2];
    const int nNeg = in_sizes[4];
    const int nTot = nPos + nNeg;

    float* cls    = (float*)d_out;
    long long vt  = (long long)out_size / 2;
    float* labels = cls + vt;

    // 1) bin edges by tag (4 edges per thread)
    {
        int threads = 256;
        int items   = (nTot + 3) / 4;
        scatter_kernel<<<(items + threads - 1) / threads, threads>>>(
            pos_src, pos_dst, neg_src, neg_dst, nPos, nTot);
    }

    // 2) overlapped zero-stream (write-through) + edge-gather
    long long nvec = (long long)out_size / 4;
    mega_kernel<<<4000, 256>>>(h_tag, h_video, (float4*)d_out, nvec);

    // 3) fold scores into zeroed output, reset cursors
    fold_kernel<<<T_DIM, 128>>>(cls, labels);
}

// round 9
// speedup vs baseline: 1.1156x; 1.1156x over previous
#include <cuda_runtime.h>
#include <cstdint>

// T = 2000 tags, V = 20000 videos, D = 768, E_POS = E_NEG = 100000
// Output layout: [cls_score (V*T f32), labels (V*T f32)]
//
// R9 structure (serial phases, but scatter hidden inside zero):
//   1) zs_kernel   : two independent roles in one launch
//        - SCATTER role (first 782 blocks): bin edges by tag (atomic
//          cursors). Latency/atomic-slice-bound, ~13us of work.
//        - ZERO role (78125 blocks): stream 320MB of zeros (evict-first).
//          DRAM-write-bound, ~45us. Scatter hides under it completely.
//        Disjoint writes (d_out vs g_cursor/g_edges) -> no hazard.
//   2) edge_kernel : one block per tag, warp-per-edge with prefetch,
//        direct atomicAdd into the zeroed output (stream-ordered after
//        zs_kernel). Measured at ~52us = LTS cap for 600MB of gathers.
//        Resets cursors (single-reader broadcast) for the next replay.
//
// NOTE (learned R7/R8): zero must NOT overlap the edge gathers — the 320MB
// store stream churns L2 and demotes the video-table reuse to DRAM misses.

#define D_DIM    768
#define T_DIM    2000
#define BIN_CAP  192      // edges/tag ~ Poisson(100); P(>192) ~ 1e-12

__device__ int      g_cursor[T_DIM];            // zero at module load
__device__ unsigned g_edges [T_DIM * BIN_CAP];  // bit31 = isPos, low = dst

// ---------------------------------------------------------------------------
// Merged zero + scatter kernel.
//   bid <  sblocks : scatter role, edge i = bid*256+tid
//   bid >= sblocks : zero role,    vec  i = (bid-sblocks)*256+tid
// ---------------------------------------------------------------------------
__global__ __launch_bounds__(256) void zs_kernel(
    const int* __restrict__ pos_src,
    const int* __restrict__ pos_dst,
    const int* __restrict__ neg_src,
    const int* __restrict__ neg_dst,
    int nPos, int nTot, int sblocks,
    float4* __restrict__ out_vec, long long nvec)
{
    const int bid = blockIdx.x;
    const int tid = threadIdx.x;

    if (bid < sblocks) {
        // ---------------- SCATTER role ----------------
        int i = bid * 256 + tid;
        if (i < nTot) {
            int t; unsigned enc;
            if (i < nPos) { t = pos_src[i];        enc = (unsigned)pos_dst[i] | 0x80000000u; }
            else          { t = neg_src[i - nPos]; enc = (unsigned)neg_dst[i - nPos]; }
            int slot = atomicAdd(&g_cursor[t], 1);
            if (slot < BIN_CAP)
                g_edges[t * BIN_CAP + slot] = enc;
        }
        return;
    }

    // -------------------- ZERO role --------------------
    long long i = (long long)(bid - sblocks) * 256 + tid;
    if (i < nvec)
        __stcs(&out_vec[i], make_float4(0.f, 0.f, 0.f, 0.f));
}

// ---------------------------------------------------------------------------
// One block per tag (2000 blocks, 8 warps). Tag row smem -> registers;
// warp-per-edge with double-buffered prefetch of the video row; direct
// atomicAdd into the zeroed output. Cursor reset: single-reader broadcast.
// ---------------------------------------------------------------------------
__global__ __launch_bounds__(256) void edge_kernel(
    const float* __restrict__ h_tag,
    const float* __restrict__ h_video,
    float*       __restrict__ cls,
    float*       __restrict__ labels)
{
    __shared__ float4 stag[D_DIM / 4];   // 3KB tag row
    __shared__ int    s_n;

    const int t   = blockIdx.x;
    const int tid = threadIdx.x;

    if (tid == 0) {
        int c = g_cursor[t];
        s_n = (c > BIN_CAP) ? BIN_CAP : c;
        g_cursor[t] = 0;                 // sole reset point (for next replay)
    }
    if (tid < D_DIM / 4)
        stag[tid] = reinterpret_cast<const float4*>(h_tag + (size_t)t * D_DIM)[tid];
    __syncthreads();

    const int lane = tid & 31;
    const int warp = tid >> 5;

    // tag row -> registers (no shared loads in the hot loop)
    float4 ta0 = stag[lane +   0];
    float4 ta1 = stag[lane +  32];
    float4 ta2 = stag[lane +  64];
    float4 ta3 = stag[lane +  96];
    float4 ta4 = stag[lane + 128];
    float4 ta5 = stag[lane + 160];

    const int n = s_n;
    const unsigned* elist = g_edges + (size_t)t * BIN_CAP;

    int i = warp;
    if (i >= n) return;

    unsigned enc = elist[i];
    const float4* bp =
        reinterpret_cast<const float4*>(h_video + (size_t)(enc & 0x7fffffffu) * D_DIM);
    float4 v0 = bp[lane +   0];
    float4 v1 = bp[lane +  32];
    float4 v2 = bp[lane +  64];
    float4 v3 = bp[lane +  96];
    float4 v4 = bp[lane + 128];
    float4 v5 = bp[lane + 160];

    while (true) {
        const int inext = i + 8;               // 8 warps per block
        const bool more = inext < n;

        // prefetch next edge's video row during the reduce
        unsigned enc_n = 0;
        float4 w0, w1, w2, w3, w4, w5;
        if (more) {
            enc_n = elist[inext];
            const float4* bn =
                reinterpret_cast<const float4*>(h_video + (size_t)(enc_n & 0x7fffffffu) * D_DIM);
            w0 = bn[lane +   0];
            w1 = bn[lane +  32];
            w2 = bn[lane +  64];
            w3 = bn[lane +  96];
            w4 = bn[lane + 128];
            w5 = bn[lane + 160];
        }

        float acc;
        acc  = ta0.x * v0.x + ta0.y * v0.y + ta0.z * v0.z + ta0.w * v0.w;
        acc += ta1.x * v1.x + ta1.y * v1.y + ta1.z * v1.z + ta1.w * v1.w;
        acc += ta2.x * v2.x + ta2.y * v2.y + ta2.z * v2.z + ta2.w * v2.w;
        acc += ta3.x * v3.x + ta3.y * v3.y + ta3.z * v3.z + ta3.w * v3.w;
        acc += ta4.x * v4.x + ta4.y * v4.y + ta4.z * v4.z + ta4.w * v4.w;
        acc += ta5.x * v5.x + ta5.y * v5.y + ta5.z * v5.z + ta5.w * v5.w;

#pragma unroll
        for (int off = 16; off > 0; off >>= 1)
            acc += __shfl_xor_sync(0xffffffffu, acc, off);

        if (lane == 0) {
            int d = (int)(enc & 0x7fffffffu);
            size_t cell = (size_t)d * T_DIM + (size_t)t;
            atomicAdd(&cls[cell], acc);
            if (enc & 0x80000000u) atomicAdd(&labels[cell], 1.0f);
        }

        if (!more) break;
        i = inext; enc = enc_n;
        v0 = w0; v1 = w1; v2 = w2; v3 = w3; v4 = w4; v5 = w5;
    }
}

// ---------------------------------------------------------------------------
extern "C" void kernel_launch(void* const* d_in, const int* in_sizes, int n_in,
                              void* d_out, int out_size)
{
    const float* h_tag   = (const float*)d_in[0];
    const float* h_video = (const float*)d_in[1];
    const int*   pos_src = (const int*)d_in[2];
    const int*   pos_dst = (const int*)d_in[3];
    const int*   neg_src = (const int*)d_in[4];
    const int*   neg_dst = (const int*)d_in[5];

    const int nPos = in_sizes[2];
    const int nNeg = in_sizes[4];
    const int nTot = nPos + nNeg;

    float* cls    = (float*)d_out;
    long long vt  = (long long)out_size / 2;
    float* labels = cls + vt;

    // 1) merged zero + scatter (scatter hides under the DRAM-bound zero)
    {
        long long nvec    = (long long)out_size / 4;
        int       sblocks = (nTot + 255) / 256;                 // 782
        long long zblocks = (nvec + 255) / 256;                 // 78125
        zs_kernel<<<(unsigned)(sblocks + zblocks), 256>>>(
            pos_src, pos_dst, neg_src, neg_dst,
            nPos, nTot, sblocks, (float4*)d_out, nvec);
    }

    // 2) edge gather + direct scatter-add (starts after zeros are done)
    edge_kernel<<<T_DIM, 256>>>(h_tag, h_video, cls, labels);
}